// round 2
// baseline (speedup 1.0000x reference)
#include <cuda_runtime.h>
#include <cstdint>

#define Gn 128
#define Sn 32
#define Nn 32
#define Dn 128
#define Ln 3
#define Hn 4
#define HDn 32
#define Tn (Gn*Sn*Nn)        // 131072
#define TOn (Gn*Nn)          // 4096
#define En 1048576
#define EOn 16384
#define NTASK 10
#define EPSn 1e-5f

// ---------------- device scratch (allocation-free) ----------------
__device__ float g_x[Tn*Dn];
__device__ float g_agg1[Tn*Dn];
__device__ float g_c1[Tn*Dn];
__device__ float g_sub[Gn*Sn*Dn];
__device__ float g_q[Gn*Sn*Dn];
__device__ float g_k[Gn*Sn*Dn];
__device__ float g_attn[Gn*Sn*Sn];
__device__ float g_xatt[TOn*Dn];
__device__ float g_agg2[TOn*Dn];
__device__ float g_c2[TOn*Dn];
__device__ float g_h2[TOn*Dn];
__device__ float g_acc[512];     // [0:128) sum1 [128:256) sq1 [256:384) sum2 [384:512) sq2
__device__ float g_coef[512];    // scale1, shift1, scale2, shift2
__device__ float g_hg[Gn*Dn];

// ---------------- edge scatter: warp per edge, float4 red ----------------
__global__ void scatter_kernel(const float* __restrict__ x,
                               const int* __restrict__ src,
                               const int* __restrict__ dst,
                               float* __restrict__ agg, int nE)
{
    int e = (blockIdx.x * blockDim.x + threadIdx.x) >> 5;
    int lane = threadIdx.x & 31;
    if (e >= nE) return;
    int s = __ldg(&src[e]);
    int d = __ldg(&dst[e]);
    const float4 v = __ldg(((const float4*)(x + (size_t)s * Dn)) + lane);
    float4* dp = ((float4*)(agg + (size_t)d * Dn)) + lane;
    asm volatile("red.global.add.v4.f32 [%0], {%1,%2,%3,%4};"
                 :: "l"(dp), "f"(v.x), "f"(v.y), "f"(v.z), "f"(v.w) : "memory");
}

// ---------------- fused GraphConv GEMM: C = A1@W1 (+ A2@W2) + bias ----------------
// Tile 128x128, 256 threads, 8x8 micro-tiles. cols fixed = 128, nrows % 128 == 0.
__global__ __launch_bounds__(256)
void conv_gemm(const float* __restrict__ A1, const float* __restrict__ A2,
               const float* __restrict__ W1, const float* __restrict__ W2,
               const float* __restrict__ bias, float* __restrict__ C)
{
    __shared__ float As[8][132];
    __shared__ float Bs[8][128];
    const int tid = threadIdx.x;
    const int tx = tid & 15;       // n block (8 cols)
    const int ty = tid >> 4;       // m block (8 rows)
    const int row0 = blockIdx.x * 128;

    float acc[8][8];
#pragma unroll
    for (int i = 0; i < 8; i++)
#pragma unroll
        for (int j = 0; j < 8; j++) acc[i][j] = 0.f;

    const int lm  = tid >> 1;           // 0..127 row within tile
    const int lk4 = (tid & 1) * 4;      // 0 or 4
    const int lbk = tid >> 5;           // 0..7
    const int lbn = (tid & 31) * 4;     // 0..124

    for (int half = 0; half < 2; half++) {
        const float* A = half ? A2 : A1;
        const float* W = half ? W2 : W1;
        if (A == nullptr) break;
        for (int kk = 0; kk < Dn; kk += 8) {
            float4 av = __ldg((const float4*)(A + (size_t)(row0 + lm) * Dn + kk + lk4));
            float4 bv = __ldg((const float4*)(W + (size_t)(kk + lbk) * Dn + lbn));
            __syncthreads();
            As[lk4 + 0][lm] = av.x;
            As[lk4 + 1][lm] = av.y;
            As[lk4 + 2][lm] = av.z;
            As[lk4 + 3][lm] = av.w;
            *(float4*)&Bs[lbk][lbn] = bv;
            __syncthreads();
#pragma unroll
            for (int k = 0; k < 8; k++) {
                float4 a0 = *(const float4*)&As[k][ty * 8];
                float4 a1 = *(const float4*)&As[k][ty * 8 + 4];
                float4 b0 = *(const float4*)&Bs[k][tx * 8];
                float4 b1 = *(const float4*)&Bs[k][tx * 8 + 4];
                float a[8] = {a0.x,a0.y,a0.z,a0.w,a1.x,a1.y,a1.z,a1.w};
                float b[8] = {b0.x,b0.y,b0.z,b0.w,b1.x,b1.y,b1.z,b1.w};
#pragma unroll
                for (int i = 0; i < 8; i++)
#pragma unroll
                    for (int j = 0; j < 8; j++)
                        acc[i][j] += a[i] * b[j];
            }
        }
    }

    float bv[8];
#pragma unroll
    for (int j = 0; j < 8; j++) bv[j] = __ldg(&bias[tx * 8 + j]);
#pragma unroll
    for (int i = 0; i < 8; i++) {
        float* cp = C + (size_t)(row0 + ty * 8 + i) * Dn + tx * 8;
        float4 o0 = make_float4(acc[i][0]+bv[0], acc[i][1]+bv[1], acc[i][2]+bv[2], acc[i][3]+bv[3]);
        float4 o1 = make_float4(acc[i][4]+bv[4], acc[i][5]+bv[5], acc[i][6]+bv[6], acc[i][7]+bv[7]);
        *(float4*)cp = o0;
        *(float4*)(cp + 4) = o1;
    }
}

// ---------------- per-column sum / sumsq ----------------
__global__ void col_stats(const float* __restrict__ X, int rows, float* __restrict__ acc)
{
    int d = threadIdx.x;  // 128
    float s = 0.f, q = 0.f;
    for (int r = blockIdx.x; r < rows; r += gridDim.x) {
        float v = X[(size_t)r * Dn + d];
        s += v; q += v * v;
    }
    atomicAdd(&acc[d], s);
    atomicAdd(&acc[Dn + d], q);
}

__global__ void bn_prep(const float* __restrict__ acc, const float* __restrict__ gamma,
                        const float* __restrict__ beta, float inv_rows, float* __restrict__ coef)
{
    int d = threadIdx.x;
    float mu = acc[d] * inv_rows;
    float var = acc[Dn + d] * inv_rows - mu * mu;
    float sc = gamma[d] * rsqrtf(var + EPSn);
    coef[d] = sc;
    coef[Dn + d] = beta[d] - mu * sc;
}

__global__ void bn_apply(const float* __restrict__ c, const float* __restrict__ coef,
                         float* __restrict__ h, int n)
{
    int idx = blockIdx.x * blockDim.x + threadIdx.x;
    if (idx >= n) return;
    int d = idx & (Dn - 1);
    h[idx] = coef[d] * c[idx] + coef[Dn + d];
}

// ---------------- sub = mean over N ----------------
__global__ void submean_kernel(const float* __restrict__ x, float* __restrict__ sub)
{
    int b = blockIdx.x;                 // g*Sn + s
    int d = threadIdx.x;                // 128
    const float* xp = x + (size_t)b * Nn * Dn;
    float s = 0.f;
#pragma unroll 8
    for (int n = 0; n < Nn; n++) s += xp[n * Dn + d];
    sub[(size_t)b * Dn + d] = s * (1.f / Nn);
}

// ---------------- attention: per-graph 32x32, head-averaged softmax ----------------
__global__ void attn_kernel(const float* __restrict__ q, const float* __restrict__ k,
                            float* __restrict__ attn)
{
    int g = blockIdx.x;
    int tid = threadIdx.x;              // 128
    __shared__ float qs[Dn * 33];       // transposed [c][qi], stride 33
    __shared__ float ks[Sn * Dn];
    __shared__ float at[Sn * Sn];
    const float* qg = q + (size_t)g * Sn * Dn;
    const float* kg = k + (size_t)g * Sn * Dn;
    for (int i = tid; i < Sn * Dn; i += 128) {
        int qi = i >> 7, c = i & 127;
        qs[c * 33 + qi] = qg[i];
        ks[i] = kg[i];
    }
    for (int i = tid; i < Sn * Sn; i += 128) at[i] = 0.f;
    __syncthreads();

    int h = tid >> 5;
    int qi = tid & 31;
    const float scale = 0.17677669529663687f;  // 1/sqrt(32)
    float sc[Sn];
    float mx = -1e30f;
#pragma unroll
    for (int j = 0; j < Sn; j++) {
        float dsum = 0.f;
#pragma unroll
        for (int hd = 0; hd < HDn; hd++)
            dsum += qs[(h * HDn + hd) * 33 + qi] * ks[j * Dn + h * HDn + hd];
        sc[j] = dsum * scale;
        mx = fmaxf(mx, sc[j]);
    }
    float se = 0.f;
#pragma unroll
    for (int j = 0; j < Sn; j++) { sc[j] = expf(sc[j] - mx); se += sc[j]; }
    float inv = 0.25f / se;   // head-mean folded in
#pragma unroll
    for (int j = 0; j < Sn; j++) atomicAdd(&at[qi * Sn + j], sc[j] * inv);
    __syncthreads();
    for (int i = tid; i < Sn * Sn; i += 128) attn[(size_t)g * Sn * Sn + i] = at[i];
}

// ---------------- x_atten[g,n,d] = sum_s attn[g,s,n]*x[g,s,n,d] ----------------
__global__ void xatten_kernel(const float* __restrict__ x, const float* __restrict__ attn,
                              float* __restrict__ xatt)
{
    int b = blockIdx.x;                 // g*Nn + n
    int g = b >> 5, n = b & 31;
    int d = threadIdx.x;                // 128
    __shared__ float coef[Sn];
    if (d < Sn) coef[d] = attn[(size_t)g * Sn * Sn + d * Sn + n];
    __syncthreads();
    float acc = 0.f;
#pragma unroll 8
    for (int s = 0; s < Sn; s++)
        acc += coef[s] * x[(size_t)((g * Sn + s) * Nn + n) * Dn + d];
    xatt[(size_t)b * Dn + d] = acc;
}

// ---------------- x = relu(BN1(c1) + h2 broadcast) ----------------
__global__ void combine_kernel(const float* __restrict__ c1, const float* __restrict__ coef1,
                               const float* __restrict__ h2, float* __restrict__ x)
{
    int idx = blockIdx.x * blockDim.x + threadIdx.x;
    if (idx >= Tn * Dn) return;
    int d = idx & (Dn - 1);
    int t = idx >> 7;
    int n = t & 31;
    int g = t >> 10;
    float v = coef1[d] * c1[idx] + coef1[Dn + d] + h2[(size_t)((g << 5) + n) * Dn + d];
    x[idx] = fmaxf(v, 0.f);
}

// ---------------- graph pooling ----------------
__global__ void pool_kernel(const float* __restrict__ x, float* __restrict__ hg)
{
    int g = blockIdx.x;
    int d = threadIdx.x;  // 128
    const float* xp = x + (size_t)g * Sn * Nn * Dn;
    float s = 0.f;
    for (int r = 0; r < Sn * Nn; r++) s += xp[(size_t)r * Dn + d];
    hg[(size_t)g * Dn + d] = s * (1.f / (Sn * Nn));
}

// ---------------- MLP head ----------------
__global__ void mlp_kernel(const float* __restrict__ hg, const float* __restrict__ Wf1,
                           const float* __restrict__ bf1, const float* __restrict__ Wf2,
                           const float* __restrict__ bf2, float* __restrict__ out)
{
    int g = blockIdx.x;
    int tid = threadIdx.x;  // 256
    __shared__ float hv[Dn];
    __shared__ float hid[2 * Dn];
    if (tid < Dn) hv[tid] = hg[(size_t)g * Dn + tid];
    __syncthreads();
    float a = bf1[tid];
#pragma unroll 8
    for (int k2 = 0; k2 < Dn; k2++) a += hv[k2] * Wf1[(size_t)k2 * 2 * Dn + tid];
    hid[tid] = fmaxf(a, 0.f);
    __syncthreads();
    if (tid < NTASK) {
        float o = bf2[tid];
        for (int k2 = 0; k2 < 2 * Dn; k2++) o += hid[k2] * Wf2[(size_t)k2 * NTASK + tid];
        out[(size_t)g * NTASK + tid] = o;
    }
}

__global__ void heatmap_kernel(const float* __restrict__ attn, float* __restrict__ out)
{
    int i = blockIdx.x * blockDim.x + threadIdx.x;
    if (i < Sn * Sn) out[i] = attn[(size_t)(Gn - 1) * Sn * Sn + i];
}

// ---------------- host orchestration ----------------
extern "C" void kernel_launch(void* const* d_in, const int* in_sizes, int n_in,
                              void* d_out, int out_size)
{
    const float* x_in = (const float*)d_in[0];
    const int*   ei   = (const int*)d_in[1];
    const int*   oei  = (const int*)d_in[2];
    const float* Wr1 = (const float*)d_in[3];
    const float* Wn1 = (const float*)d_in[4];
    const float* b1  = (const float*)d_in[5];
    const float* g1  = (const float*)d_in[6];
    const float* be1 = (const float*)d_in[7];
    const float* Wr2 = (const float*)d_in[8];
    const float* Wn2 = (const float*)d_in[9];
    const float* b2  = (const float*)d_in[10];
    const float* g2  = (const float*)d_in[11];
    const float* be2 = (const float*)d_in[12];
    const float* Wq  = (const float*)d_in[13];
    const float* bq  = (const float*)d_in[14];
    const float* Wk  = (const float*)d_in[15];
    const float* bk  = (const float*)d_in[16];
    const float* Wf1 = (const float*)d_in[17];
    const float* bf1 = (const float*)d_in[18];
    const float* Wf2 = (const float*)d_in[19];
    const float* bf2 = (const float*)d_in[20];
    float* out = (float*)d_out;

    float *px, *pagg1, *pc1, *psub, *pq, *pk, *pattn, *pxatt, *pagg2, *pc2, *ph2, *pacc, *pcoef, *phg;
    cudaGetSymbolAddress((void**)&px,    g_x);
    cudaGetSymbolAddress((void**)&pagg1, g_agg1);
    cudaGetSymbolAddress((void**)&pc1,   g_c1);
    cudaGetSymbolAddress((void**)&psub,  g_sub);
    cudaGetSymbolAddress((void**)&pq,    g_q);
    cudaGetSymbolAddress((void**)&pk,    g_k);
    cudaGetSymbolAddress((void**)&pattn, g_attn);
    cudaGetSymbolAddress((void**)&pxatt, g_xatt);
    cudaGetSymbolAddress((void**)&pagg2, g_agg2);
    cudaGetSymbolAddress((void**)&pc2,   g_c2);
    cudaGetSymbolAddress((void**)&ph2,   g_h2);
    cudaGetSymbolAddress((void**)&pacc,  g_acc);
    cudaGetSymbolAddress((void**)&pcoef, g_coef);
    cudaGetSymbolAddress((void**)&phg,   g_hg);

    cudaMemcpyAsync(px, x_in, sizeof(float) * Tn * Dn, cudaMemcpyDeviceToDevice, 0);

    for (int i = 0; i < Ln; i++) {
        const size_t wOff = (size_t)i * Dn * Dn;
        const size_t vOff = (size_t)i * Dn;

        cudaMemsetAsync(pagg1, 0, sizeof(float) * Tn * Dn, 0);
        cudaMemsetAsync(pagg2, 0, sizeof(float) * TOn * Dn, 0);
        cudaMemsetAsync(pacc,  0, sizeof(float) * 512, 0);

        // subgraph-level GraphConv
        scatter_kernel<<<(En * 32) / 256, 256>>>(px, ei, ei + En, pagg1, En);
        conv_gemm<<<Tn / 128, 256>>>(px, pagg1, Wr1 + wOff, Wn1 + wOff, b1 + vOff, pc1);
        col_stats<<<1024, 128>>>(pc1, Tn, pacc);
        bn_prep<<<1, 128>>>(pacc, g1 + vOff, be1 + vOff, 1.f / Tn, pcoef);

        // attention branch
        submean_kernel<<<Gn * Sn, 128>>>(px, psub);
        conv_gemm<<<(Gn * Sn) / 128, 256>>>(psub, nullptr, Wq + wOff, nullptr, bq + vOff, pq);
        conv_gemm<<<(Gn * Sn) / 128, 256>>>(psub, nullptr, Wk + wOff, nullptr, bk + vOff, pk);
        attn_kernel<<<Gn, 128>>>(pq, pk, pattn);
        xatten_kernel<<<Gn * Nn, 128>>>(px, pattn, pxatt);

        // original-graph GraphConv
        scatter_kernel<<<(EOn * 32) / 256, 256>>>(pxatt, oei, oei + EOn, pagg2, EOn);
        conv_gemm<<<TOn / 128, 256>>>(pxatt, pagg2, Wr2 + wOff, Wn2 + wOff, b2 + vOff, pc2);
        col_stats<<<64, 128>>>(pc2, TOn, pacc + 256);
        bn_prep<<<1, 128>>>(pacc + 256, g2 + vOff, be2 + vOff, 1.f / TOn, pcoef + 256);
        bn_apply<<<(TOn * Dn) / 256, 256>>>(pc2, pcoef + 256, ph2, TOn * Dn);

        // x = relu(h1 + h2 broadcast)
        combine_kernel<<<(Tn * Dn) / 256, 256>>>(pc1, pcoef, ph2, px);
    }

    pool_kernel<<<Gn, 128>>>(px, phg);
    mlp_kernel<<<Gn, 256>>>(phg, Wf1, bf1, Wf2, bf2, out);
    heatmap_kernel<<<4, 256>>>(pattn, out + Gn * NTASK);
}

// round 4
// speedup vs baseline: 1.6948x; 1.6948x over previous
#include <cuda_runtime.h>
#include <cstdint>

#define Gn 128
#define Sn 32
#define Nn 32
#define Dn 128
#define Ln 3
#define Hn 4
#define HDn 32
#define Tn (Gn*Sn*Nn)        // 131072
#define TOn (Gn*Nn)          // 4096
#define En 1048576
#define EOn 16384
#define NTASK 10
#define EPSn 1e-5f

// ---------------- device scratch (allocation-free) ----------------
__device__ float g_x[Tn*Dn];
__device__ float g_agg1[Tn*Dn];
__device__ float g_c1[Tn*Dn];
__device__ float g_sub[Gn*Sn*Dn];
__device__ float g_q[Gn*Sn*Dn];
__device__ float g_k[Gn*Sn*Dn];
__device__ float g_attn[Gn*Sn*Sn];
__device__ float g_xatt[TOn*Dn];
__device__ float g_agg2[TOn*Dn];
__device__ float g_c2[TOn*Dn];
__device__ float g_h2[TOn*Dn];
__device__ float g_acc[512];     // [0:128) sum1 [128:256) sq1 [256:384) sum2 [384:512) sq2
__device__ float g_coef[512];    // scale1, shift1, scale2, shift2
__device__ float g_hg[Gn*Dn];

// ---------------- edge scatter: warp per edge, float4 red ----------------
__global__ void scatter_kernel(const float* __restrict__ x,
                               const int* __restrict__ src,
                               const int* __restrict__ dst,
                               float* __restrict__ agg, int nE)
{
    int e = (blockIdx.x * blockDim.x + threadIdx.x) >> 5;
    int lane = threadIdx.x & 31;
    if (e >= nE) return;
    int s = __ldg(&src[e]);
    int d = __ldg(&dst[e]);
    const float4 v = __ldg(((const float4*)(x + (size_t)s * Dn)) + lane);
    float4* dp = ((float4*)(agg + (size_t)d * Dn)) + lane;
    asm volatile("red.global.add.v4.f32 [%0], {%1,%2,%3,%4};"
                 :: "l"(dp), "f"(v.x), "f"(v.y), "f"(v.z), "f"(v.w) : "memory");
}

// ---------------- cp.async helpers ----------------
__device__ __forceinline__ void cpasync16(void* dst, const void* src)
{
    uint32_t d = (uint32_t)__cvta_generic_to_shared(dst);
    asm volatile("cp.async.cg.shared.global [%0], [%1], 16;" :: "r"(d), "l"(src));
}
__device__ __forceinline__ void cpasync_commit() { asm volatile("cp.async.commit_group;"); }
template<int N> __device__ __forceinline__ void cpasync_wait() { asm volatile("cp.async.wait_group %0;" :: "n"(N)); }

__device__ __forceinline__ uint32_t f2tf32(float v)
{
    uint32_t u;
    asm("cvt.rna.tf32.f32 %0, %1;" : "=r"(u) : "f"(v));
    return u;
}

// ---------------- tf32 tensor-core GEMM: C = A1@W1 (+ A2@W2) + bias ----------------
// 128x128 tile, BK=16, 256 threads (8 warps, 2x4), warp tile 64x32 via m16n8k8.
// Optionally fuses per-column sum/sumsq (of biased output) into statAcc[0:128]/[128:256].
#define ASTR 20
#define BSTR 136
__global__ __launch_bounds__(256)
void conv_gemm_tf32(const float* __restrict__ A1, const float* __restrict__ A2,
                    const float* __restrict__ W1, const float* __restrict__ W2,
                    const float* __restrict__ bias, float* __restrict__ C,
                    float* __restrict__ statAcc)
{
    __shared__ float As[2 * 128 * ASTR];
    __shared__ float Bs[2 * 16 * BSTR];

    const int tid = threadIdx.x;
    const int wid = tid >> 5, lane = tid & 31;
    const int wm = wid >> 2, wn = wid & 3;
    const int group = lane >> 2, tig = lane & 3;
    const int row0 = blockIdx.x * 128;
    const int nst = (A2 != nullptr) ? 16 : 8;   // stages of BK=16 over K (2 halves of 128)

    float acc[4][4][4];
#pragma unroll
    for (int i = 0; i < 4; i++)
#pragma unroll
        for (int j = 0; j < 4; j++)
#pragma unroll
            for (int r = 0; r < 4; r++) acc[i][j][r] = 0.f;

    // --- stage loader: copy A[128x16] and W[16x128] for stage kt into buffer (kt&1) ---
    auto load_stage = [&](int kt) {
        const float* A = (kt >= 8) ? A2 : A1;
        const float* W = (kt >= 8) ? W2 : W1;
        const int kg = (kt & 7) * 16;
        float* as = As + (kt & 1) * 128 * ASTR;
        float* bs = Bs + (kt & 1) * 16 * BSTR;
#pragma unroll
        for (int p = 0; p < 2; p++) {
            int f = tid + p * 256;            // A: 512 float4 total
            int row = f >> 2, kq = f & 3;
            cpasync16(as + row * ASTR + kq * 4,
                      A + (size_t)(row0 + row) * Dn + kg + kq * 4);
        }
#pragma unroll
        for (int p = 0; p < 2; p++) {
            int f = tid + p * 256;            // B: 512 float4 total
            int row = f >> 5, nq = f & 31;
            cpasync16(bs + row * BSTR + nq * 4,
                      W + (size_t)(kg + row) * Dn + nq * 4);
        }
        cpasync_commit();
    };

    load_stage(0);
    for (int s = 0; s < nst; s++) {
        if (s + 1 < nst) { load_stage(s + 1); cpasync_wait<1>(); }
        else             { cpasync_wait<0>(); }
        __syncthreads();

        const float* sa = As + (s & 1) * 128 * ASTR;
        const float* sb = Bs + (s & 1) * 16 * BSTR;
#pragma unroll
        for (int ks = 0; ks < 2; ks++) {
            const int k0 = ks * 8;
            uint32_t ua[4][4], ub[4][2];
#pragma unroll
            for (int i = 0; i < 4; i++) {
                int r = wm * 64 + i * 16 + group;
                ua[i][0] = f2tf32(sa[r * ASTR + k0 + tig]);
                ua[i][1] = f2tf32(sa[(r + 8) * ASTR + k0 + tig]);
                ua[i][2] = f2tf32(sa[r * ASTR + k0 + 4 + tig]);
                ua[i][3] = f2tf32(sa[(r + 8) * ASTR + k0 + 4 + tig]);
            }
#pragma unroll
            for (int j = 0; j < 4; j++) {
                int n = wn * 32 + j * 8 + group;
                ub[j][0] = f2tf32(sb[(k0 + tig) * BSTR + n]);
                ub[j][1] = f2tf32(sb[(k0 + 4 + tig) * BSTR + n]);
            }
#pragma unroll
            for (int i = 0; i < 4; i++)
#pragma unroll
                for (int j = 0; j < 4; j++) {
                    asm volatile(
                        "mma.sync.aligned.m16n8k8.row.col.f32.tf32.tf32.f32 "
                        "{%0,%1,%2,%3}, {%4,%5,%6,%7}, {%8,%9}, {%0,%1,%2,%3};"
                        : "+f"(acc[i][j][0]), "+f"(acc[i][j][1]),
                          "+f"(acc[i][j][2]), "+f"(acc[i][j][3])
                        : "r"(ua[i][0]), "r"(ua[i][1]), "r"(ua[i][2]), "r"(ua[i][3]),
                          "r"(ub[j][0]), "r"(ub[j][1]));
                }
        }
        __syncthreads();
    }

    // --- epilogue: bias add, store, fused column stats ---
#pragma unroll
    for (int j = 0; j < 4; j++) {
        const int n = wn * 32 + j * 8 + tig * 2;
        const float bv0 = __ldg(&bias[n]);
        const float bv1 = __ldg(&bias[n + 1]);
        float s0 = 0.f, s1 = 0.f, q0 = 0.f, q1 = 0.f;
#pragma unroll
        for (int i = 0; i < 4; i++) {
            const int row = row0 + wm * 64 + i * 16 + group;
            float v0 = acc[i][j][0] + bv0;
            float v1 = acc[i][j][1] + bv1;
            float v2 = acc[i][j][2] + bv0;
            float v3 = acc[i][j][3] + bv1;
            *(float2*)(C + (size_t)row * Dn + n)       = make_float2(v0, v1);
            *(float2*)(C + (size_t)(row + 8) * Dn + n) = make_float2(v2, v3);
            s0 += v0 + v2;  q0 += v0 * v0 + v2 * v2;
            s1 += v1 + v3;  q1 += v1 * v1 + v3 * v3;
        }
        if (statAcc) {
#pragma unroll
            for (int off = 4; off <= 16; off <<= 1) {
                s0 += __shfl_down_sync(0xffffffffu, s0, off);
                s1 += __shfl_down_sync(0xffffffffu, s1, off);
                q0 += __shfl_down_sync(0xffffffffu, q0, off);
                q1 += __shfl_down_sync(0xffffffffu, q1, off);
            }
            if (group == 0) {
                atomicAdd(&statAcc[n], s0);
                atomicAdd(&statAcc[Dn + n], q0);
                atomicAdd(&statAcc[n + 1], s1);
                atomicAdd(&statAcc[Dn + n + 1], q1);
            }
        }
    }
}

__global__ void bn_prep(const float* __restrict__ acc, const float* __restrict__ gamma,
                        const float* __restrict__ beta, float inv_rows, float* __restrict__ coef)
{
    int d = threadIdx.x;
    float mu = acc[d] * inv_rows;
    float var = acc[Dn + d] * inv_rows - mu * mu;
    float sc = gamma[d] * rsqrtf(var + EPSn);
    coef[d] = sc;
    coef[Dn + d] = beta[d] - mu * sc;
}

__global__ void bn_apply(const float* __restrict__ c, const float* __restrict__ coef,
                         float* __restrict__ h, int n)
{
    int idx = blockIdx.x * blockDim.x + threadIdx.x;
    if (idx >= n) return;
    int d = idx & (Dn - 1);
    h[idx] = coef[d] * c[idx] + coef[Dn + d];
}

// ---------------- sub = mean over N ----------------
__global__ void submean_kernel(const float* __restrict__ x, float* __restrict__ sub)
{
    int b = blockIdx.x;                 // g*Sn + s
    int d = threadIdx.x;                // 128
    const float* xp = x + (size_t)b * Nn * Dn;
    float s = 0.f;
#pragma unroll 8
    for (int n = 0; n < Nn; n++) s += xp[n * Dn + d];
    sub[(size_t)b * Dn + d] = s * (1.f / Nn);
}

// ---------------- attention: per-graph 32x32, head-averaged softmax ----------------
__global__ void attn_kernel(const float* __restrict__ q, const float* __restrict__ k,
                            float* __restrict__ attn)
{
    int g = blockIdx.x;
    int tid = threadIdx.x;              // 128
    __shared__ float qs[Dn * 33];       // transposed [c][qi], stride 33
    __shared__ float ks[Sn * Dn];
    __shared__ float at[Sn * Sn];
    const float* qg = q + (size_t)g * Sn * Dn;
    const float* kg = k + (size_t)g * Sn * Dn;
    for (int i = tid; i < Sn * Dn; i += 128) {
        int qi = i >> 7, c = i & 127;
        qs[c * 33 + qi] = qg[i];
        ks[i] = kg[i];
    }
    for (int i = tid; i < Sn * Sn; i += 128) at[i] = 0.f;
    __syncthreads();

    int h = tid >> 5;
    int qi = tid & 31;
    const float scale = 0.17677669529663687f;  // 1/sqrt(32)
    float sc[Sn];
    float mx = -1e30f;
#pragma unroll
    for (int j = 0; j < Sn; j++) {
        float dsum = 0.f;
#pragma unroll
        for (int hd = 0; hd < HDn; hd++)
            dsum += qs[(h * HDn + hd) * 33 + qi] * ks[j * Dn + h * HDn + hd];
        sc[j] = dsum * scale;
        mx = fmaxf(mx, sc[j]);
    }
    float se = 0.f;
#pragma unroll
    for (int j = 0; j < Sn; j++) { sc[j] = expf(sc[j] - mx); se += sc[j]; }
    float inv = 0.25f / se;   // head-mean folded in
#pragma unroll
    for (int j = 0; j < Sn; j++) atomicAdd(&at[qi * Sn + j], sc[j] * inv);
    __syncthreads();
    for (int i = tid; i < Sn * Sn; i += 128) attn[(size_t)g * Sn * Sn + i] = at[i];
}

// ---------------- x_atten[g,n,d] = sum_s attn[g,s,n]*x[g,s,n,d] ----------------
__global__ void xatten_kernel(const float* __restrict__ x, const float* __restrict__ attn,
                              float* __restrict__ xatt)
{
    int b = blockIdx.x;                 // g*Nn + n
    int g = b >> 5, n = b & 31;
    int d = threadIdx.x;                // 128
    __shared__ float coef[Sn];
    if (d < Sn) coef[d] = attn[(size_t)g * Sn * Sn + d * Sn + n];
    __syncthreads();
    float acc = 0.f;
#pragma unroll 8
    for (int s = 0; s < Sn; s++)
        acc += coef[s] * x[(size_t)((g * Sn + s) * Nn + n) * Dn + d];
    xatt[(size_t)b * Dn + d] = acc;
}

// ---------------- x = relu(BN1(c1) + h2 broadcast) ----------------
__global__ void combine_kernel(const float* __restrict__ c1, const float* __restrict__ coef1,
                               const float* __restrict__ h2, float* __restrict__ x)
{
    int idx = blockIdx.x * blockDim.x + threadIdx.x;
    if (idx >= Tn * Dn) return;
    int d = idx & (Dn - 1);
    int t = idx >> 7;
    int n = t & 31;
    int g = t >> 10;
    float v = coef1[d] * c1[idx] + coef1[Dn + d] + h2[(size_t)((g << 5) + n) * Dn + d];
    x[idx] = fmaxf(v, 0.f);
}

// ---------------- graph pooling ----------------
__global__ void pool_kernel(const float* __restrict__ x, float* __restrict__ hg)
{
    int g = blockIdx.x;
    int d = threadIdx.x;  // 128
    const float* xp = x + (size_t)g * Sn * Nn * Dn;
    float s = 0.f;
    for (int r = 0; r < Sn * Nn; r++) s += xp[(size_t)r * Dn + d];
    hg[(size_t)g * Dn + d] = s * (1.f / (Sn * Nn));
}

// ---------------- MLP head ----------------
__global__ void mlp_kernel(const float* __restrict__ hg, const float* __restrict__ Wf1,
                           const float* __restrict__ bf1, const float* __restrict__ Wf2,
                           const float* __restrict__ bf2, float* __restrict__ out)
{
    int g = blockIdx.x;
    int tid = threadIdx.x;  // 256
    __shared__ float hv[Dn];
    __shared__ float hid[2 * Dn];
    if (tid < Dn) hv[tid] = hg[(size_t)g * Dn + tid];
    __syncthreads();
    float a = bf1[tid];
#pragma unroll 8
    for (int k2 = 0; k2 < Dn; k2++) a += hv[k2] * Wf1[(size_t)k2 * 2 * Dn + tid];
    hid[tid] = fmaxf(a, 0.f);
    __syncthreads();
    if (tid < NTASK) {
        float o = bf2[tid];
        for (int k2 = 0; k2 < 2 * Dn; k2++) o += hid[k2] * Wf2[(size_t)k2 * NTASK + tid];
        out[(size_t)g * NTASK + tid] = o;
    }
}

__global__ void heatmap_kernel(const float* __restrict__ attn, float* __restrict__ out)
{
    int i = blockIdx.x * blockDim.x + threadIdx.x;
    if (i < Sn * Sn) out[i] = attn[(size_t)(Gn - 1) * Sn * Sn + i];
}

// ---------------- host orchestration ----------------
extern "C" void kernel_launch(void* const* d_in, const int* in_sizes, int n_in,
                              void* d_out, int out_size)
{
    const float* x_in = (const float*)d_in[0];
    const int*   ei   = (const int*)d_in[1];
    const int*   oei  = (const int*)d_in[2];
    const float* Wr1 = (const float*)d_in[3];
    const float* Wn1 = (const float*)d_in[4];
    const float* b1  = (const float*)d_in[5];
    const float* g1  = (const float*)d_in[6];
    const float* be1 = (const float*)d_in[7];
    const float* Wr2 = (const float*)d_in[8];
    const float* Wn2 = (const float*)d_in[9];
    const float* b2  = (const float*)d_in[10];
    const float* g2  = (const float*)d_in[11];
    const float* be2 = (const float*)d_in[12];
    const float* Wq  = (const float*)d_in[13];
    const float* bq  = (const float*)d_in[14];
    const float* Wk  = (const float*)d_in[15];
    const float* bk  = (const float*)d_in[16];
    const float* Wf1 = (const float*)d_in[17];
    const float* bf1 = (const float*)d_in[18];
    const float* Wf2 = (const float*)d_in[19];
    const float* bf2 = (const float*)d_in[20];
    float* out = (float*)d_out;

    float *px, *pagg1, *pc1, *psub, *pq, *pk, *pattn, *pxatt, *pagg2, *pc2, *ph2, *pacc, *pcoef, *phg;
    cudaGetSymbolAddress((void**)&px,    g_x);
    cudaGetSymbolAddress((void**)&pagg1, g_agg1);
    cudaGetSymbolAddress((void**)&pc1,   g_c1);
    cudaGetSymbolAddress((void**)&psub,  g_sub);
    cudaGetSymbolAddress((void**)&pq,    g_q);
    cudaGetSymbolAddress((void**)&pk,    g_k);
    cudaGetSymbolAddress((void**)&pattn, g_attn);
    cudaGetSymbolAddress((void**)&pxatt, g_xatt);
    cudaGetSymbolAddress((void**)&pagg2, g_agg2);
    cudaGetSymbolAddress((void**)&pc2,   g_c2);
    cudaGetSymbolAddress((void**)&ph2,   g_h2);
    cudaGetSymbolAddress((void**)&pacc,  g_acc);
    cudaGetSymbolAddress((void**)&pcoef, g_coef);
    cudaGetSymbolAddress((void**)&phg,   g_hg);

    const float* xcur = x_in;   // layer 0 reads harness input directly

    for (int i = 0; i < Ln; i++) {
        const size_t wOff = (size_t)i * Dn * Dn;
        const size_t vOff = (size_t)i * Dn;

        cudaMemsetAsync(pagg1, 0, sizeof(float) * Tn * Dn, 0);
        cudaMemsetAsync(pagg2, 0, sizeof(float) * TOn * Dn, 0);
        cudaMemsetAsync(pacc,  0, sizeof(float) * 512, 0);

        // subgraph-level GraphConv (+ fused BN stats)
        scatter_kernel<<<(En * 32) / 256, 256>>>(xcur, ei, ei + En, pagg1, En);
        conv_gemm_tf32<<<Tn / 128, 256>>>(xcur, pagg1, Wr1 + wOff, Wn1 + wOff, b1 + vOff, pc1, pacc);
        bn_prep<<<1, 128>>>(pacc, g1 + vOff, be1 + vOff, 1.f / Tn, pcoef);

        // attention branch
        submean_kernel<<<Gn * Sn, 128>>>(xcur, psub);
        conv_gemm_tf32<<<(Gn * Sn) / 128, 256>>>(psub, nullptr, Wq + wOff, nullptr, bq + vOff, pq, nullptr);
        conv_gemm_tf32<<<(Gn * Sn) / 128, 256>>>(psub, nullptr, Wk + wOff, nullptr, bk + vOff, pk, nullptr);
        attn_kernel<<<Gn, 128>>>(pq, pk, pattn);
        xatten_kernel<<<Gn * Nn, 128>>>(xcur, pattn, pxatt);

        // original-graph GraphConv (+ fused BN stats)
        scatter_kernel<<<(EOn * 32) / 256, 256>>>(pxatt, oei, oei + EOn, pagg2, EOn);
        conv_gemm_tf32<<<TOn / 128, 256>>>(pxatt, pagg2, Wr2 + wOff, Wn2 + wOff, b2 + vOff, pc2, pacc + 256);
        bn_prep<<<1, 128>>>(pacc + 256, g2 + vOff, be2 + vOff, 1.f / TOn, pcoef + 256);
        bn_apply<<<(TOn * Dn) / 256, 256>>>(pc2, pcoef + 256, ph2, TOn * Dn);

        // x = relu(h1 + h2 broadcast)
        combine_kernel<<<(Tn * Dn) / 256, 256>>>(pc1, pcoef, ph2, px);
        xcur = px;
    }

    pool_kernel<<<Gn, 128>>>(px, phg);
    mlp_kernel<<<Gn, 256>>>(phg, Wf1, bf1, Wf2, bf2, out);
    heatmap_kernel<<<4, 256>>>(pattn, out + Gn * NTASK);
}

// round 5
// speedup vs baseline: 1.8078x; 1.0667x over previous
#include <cuda_runtime.h>
#include <cstdint>

#define Gn 128
#define Sn 32
#define Nn 32
#define Dn 128
#define Ln 3
#define Hn 4
#define HDn 32
#define Tn (Gn*Sn*Nn)        // 131072
#define TOn (Gn*Nn)          // 4096
#define En 1048576
#define EOn 16384
#define NTASK 10
#define EPSn 1e-5f

// ---------------- device scratch (allocation-free) ----------------
__device__ float g_x[Tn*Dn];
__device__ float g_agg1[Tn*Dn];
__device__ float g_c1[Tn*Dn];
__device__ float g_sub[Gn*Sn*Dn];
__device__ float g_q[Gn*Sn*Dn];
__device__ float g_k[Gn*Sn*Dn];
__device__ float g_attn[Gn*Sn*Sn];
__device__ float g_xatt[TOn*Dn];
__device__ float g_agg2[TOn*Dn];
__device__ float g_c2[TOn*Dn];
__device__ float g_h2[TOn*Dn];
__device__ float g_acc[512];
__device__ float g_coef[512];
__device__ float g_hg[Gn*Dn];
// CSR scratch (big graph)
__device__ int g_deg[Tn];
__device__ int g_off[Tn + 1];
__device__ int g_cur[Tn];
__device__ int g_srcs[En];
// CSR scratch (original graph)
__device__ int g_odeg[TOn];
__device__ int g_ooff[TOn + 1];
__device__ int g_ocur[TOn];
__device__ int g_osrcs[EOn];

// ---------------- CSR build ----------------
__global__ void hist_kernel(const int* __restrict__ dst, int* __restrict__ deg, int nE)
{
    int e = blockIdx.x * blockDim.x + threadIdx.x;
    if (e < nE) atomicAdd(&deg[__ldg(&dst[e])], 1);
}

// single-block exclusive scan of n counters (n % 1024 == 0), writes off[0..n] and cursor copy
__global__ __launch_bounds__(1024)
void scan_kernel(const int* __restrict__ deg, int* __restrict__ off,
                 int* __restrict__ cur, int n)
{
    __shared__ int part[1024];
    const int t = threadIdx.x;
    const int chunk = n / 1024;
    const int base = t * chunk;
    int s = 0;
    for (int i = 0; i < chunk; i++) s += deg[base + i];
    part[t] = s;
    __syncthreads();
    for (int d = 1; d < 1024; d <<= 1) {
        int v = (t >= d) ? part[t - d] : 0;
        __syncthreads();
        part[t] += v;
        __syncthreads();
    }
    int run = (t > 0) ? part[t - 1] : 0;
    for (int i = 0; i < chunk; i++) {
        off[base + i] = run;
        cur[base + i] = run;
        run += deg[base + i];
    }
    if (t == 1023) off[n] = run;
}

__global__ void fill_kernel(const int* __restrict__ src, const int* __restrict__ dst,
                            int* __restrict__ cur, int* __restrict__ srcs, int nE)
{
    int e = blockIdx.x * blockDim.x + threadIdx.x;
    if (e >= nE) return;
    int d = __ldg(&dst[e]);
    int pos = atomicAdd(&cur[d], 1);
    srcs[pos] = __ldg(&src[e]);
}

// ---------------- CSR gather: warp per node, float4 per lane, non-atomic ----------------
__global__ void gather_kernel(const float* __restrict__ x, const int* __restrict__ off,
                              const int* __restrict__ srcs, float* __restrict__ agg,
                              int nNodes)
{
    int node = (blockIdx.x * blockDim.x + threadIdx.x) >> 5;
    int lane = threadIdx.x & 31;
    if (node >= nNodes) return;
    int e0 = __ldg(&off[node]);
    int e1 = __ldg(&off[node + 1]);
    float4 a0 = make_float4(0.f, 0.f, 0.f, 0.f);
    float4 a1 = make_float4(0.f, 0.f, 0.f, 0.f);
    int e = e0;
    for (; e + 1 < e1; e += 2) {
        int sA = __ldg(&srcs[e]);
        int sB = __ldg(&srcs[e + 1]);
        float4 va = __ldg(((const float4*)(x + (size_t)sA * Dn)) + lane);
        float4 vb = __ldg(((const float4*)(x + (size_t)sB * Dn)) + lane);
        a0.x += va.x; a0.y += va.y; a0.z += va.z; a0.w += va.w;
        a1.x += vb.x; a1.y += vb.y; a1.z += vb.z; a1.w += vb.w;
    }
    if (e < e1) {
        int sA = __ldg(&srcs[e]);
        float4 va = __ldg(((const float4*)(x + (size_t)sA * Dn)) + lane);
        a0.x += va.x; a0.y += va.y; a0.z += va.z; a0.w += va.w;
    }
    a0.x += a1.x; a0.y += a1.y; a0.z += a1.z; a0.w += a1.w;
    ((float4*)(agg + (size_t)node * Dn))[lane] = a0;
}

// ---------------- cp.async helpers ----------------
__device__ __forceinline__ void cpasync16(void* dst, const void* src)
{
    uint32_t d = (uint32_t)__cvta_generic_to_shared(dst);
    asm volatile("cp.async.cg.shared.global [%0], [%1], 16;" :: "r"(d), "l"(src));
}
__device__ __forceinline__ void cpasync_commit() { asm volatile("cp.async.commit_group;"); }
template<int N> __device__ __forceinline__ void cpasync_wait() { asm volatile("cp.async.wait_group %0;" :: "n"(N)); }

__device__ __forceinline__ uint32_t f2tf32(float v)
{
    uint32_t u;
    asm("cvt.rna.tf32.f32 %0, %1;" : "=r"(u) : "f"(v));
    return u;
}

// ---------------- tf32 tensor-core GEMM: C = A1@W1 (+ A2@W2) + bias ----------------
// 128x128 tile, BK=16, 256 threads (8 warps 2x4), warp tile 64x32 via m16n8k8.
// blockIdx.y==1 selects the alternate (W1b, biasb, Cb) operand set (Q/K fusion).
// Optionally fuses per-column sum/sumsq of the biased output into statAcc.
#define ASTR 20
#define BSTR 136
__global__ __launch_bounds__(256)
void conv_gemm_tf32(const float* __restrict__ A1, const float* __restrict__ A2,
                    const float* __restrict__ W1in, const float* __restrict__ W2,
                    const float* __restrict__ biasin, float* __restrict__ Cin,
                    float* __restrict__ statAcc,
                    const float* __restrict__ W1b, const float* __restrict__ biasb,
                    float* __restrict__ Cb)
{
    __shared__ float As[2 * 128 * ASTR];
    __shared__ float Bs[2 * 16 * BSTR];

    const float* W1 = (blockIdx.y == 0) ? W1in : W1b;
    const float* bias = (blockIdx.y == 0) ? biasin : biasb;
    float* C = (blockIdx.y == 0) ? Cin : Cb;

    const int tid = threadIdx.x;
    const int wid = tid >> 5, lane = tid & 31;
    const int wm = wid >> 2, wn = wid & 3;
    const int group = lane >> 2, tig = lane & 3;
    const int row0 = blockIdx.x * 128;
    const int nst = (A2 != nullptr) ? 16 : 8;

    float acc[4][4][4];
#pragma unroll
    for (int i = 0; i < 4; i++)
#pragma unroll
        for (int j = 0; j < 4; j++)
#pragma unroll
            for (int r = 0; r < 4; r++) acc[i][j][r] = 0.f;

    auto load_stage = [&](int kt) {
        const float* A = (kt >= 8) ? A2 : A1;
        const float* W = (kt >= 8) ? W2 : W1;
        const int kg = (kt & 7) * 16;
        float* as = As + (kt & 1) * 128 * ASTR;
        float* bs = Bs + (kt & 1) * 16 * BSTR;
#pragma unroll
        for (int p = 0; p < 2; p++) {
            int f = tid + p * 256;
            int row = f >> 2, kq = f & 3;
            cpasync16(as + row * ASTR + kq * 4,
                      A + (size_t)(row0 + row) * Dn + kg + kq * 4);
        }
#pragma unroll
        for (int p = 0; p < 2; p++) {
            int f = tid + p * 256;
            int row = f >> 5, nq = f & 31;
            cpasync16(bs + row * BSTR + nq * 4,
                      W + (size_t)(kg + row) * Dn + nq * 4);
        }
        cpasync_commit();
    };

    load_stage(0);
    for (int s = 0; s < nst; s++) {
        if (s + 1 < nst) { load_stage(s + 1); cpasync_wait<1>(); }
        else             { cpasync_wait<0>(); }
        __syncthreads();

        const float* sa = As + (s & 1) * 128 * ASTR;
        const float* sb = Bs + (s & 1) * 16 * BSTR;
#pragma unroll
        for (int ks = 0; ks < 2; ks++) {
            const int k0 = ks * 8;
            uint32_t ua[4][4], ub[4][2];
#pragma unroll
            for (int i = 0; i < 4; i++) {
                int r = wm * 64 + i * 16 + group;
                ua[i][0] = f2tf32(sa[r * ASTR + k0 + tig]);
                ua[i][1] = f2tf32(sa[(r + 8) * ASTR + k0 + tig]);
                ua[i][2] = f2tf32(sa[r * ASTR + k0 + 4 + tig]);
                ua[i][3] = f2tf32(sa[(r + 8) * ASTR + k0 + 4 + tig]);
            }
#pragma unroll
            for (int j = 0; j < 4; j++) {
                int n = wn * 32 + j * 8 + group;
                ub[j][0] = f2tf32(sb[(k0 + tig) * BSTR + n]);
                ub[j][1] = f2tf32(sb[(k0 + 4 + tig) * BSTR + n]);
            }
#pragma unroll
            for (int i = 0; i < 4; i++)
#pragma unroll
                for (int j = 0; j < 4; j++) {
                    asm volatile(
                        "mma.sync.aligned.m16n8k8.row.col.f32.tf32.tf32.f32 "
                        "{%0,%1,%2,%3}, {%4,%5,%6,%7}, {%8,%9}, {%0,%1,%2,%3};"
                        : "+f"(acc[i][j][0]), "+f"(acc[i][j][1]),
                          "+f"(acc[i][j][2]), "+f"(acc[i][j][3])
                        : "r"(ua[i][0]), "r"(ua[i][1]), "r"(ua[i][2]), "r"(ua[i][3]),
                          "r"(ub[j][0]), "r"(ub[j][1]));
                }
        }
        __syncthreads();
    }

#pragma unroll
    for (int j = 0; j < 4; j++) {
        const int n = wn * 32 + j * 8 + tig * 2;
        const float bv0 = __ldg(&bias[n]);
        const float bv1 = __ldg(&bias[n + 1]);
        float s0 = 0.f, s1 = 0.f, q0 = 0.f, q1 = 0.f;
#pragma unroll
        for (int i = 0; i < 4; i++) {
            const int row = row0 + wm * 64 + i * 16 + group;
            float v0 = acc[i][j][0] + bv0;
            float v1 = acc[i][j][1] + bv1;
            float v2 = acc[i][j][2] + bv0;
            float v3 = acc[i][j][3] + bv1;
            *(float2*)(C + (size_t)row * Dn + n)       = make_float2(v0, v1);
            *(float2*)(C + (size_t)(row + 8) * Dn + n) = make_float2(v2, v3);
            s0 += v0 + v2;  q0 += v0 * v0 + v2 * v2;
            s1 += v1 + v3;  q1 += v1 * v1 + v3 * v3;
        }
        if (statAcc) {
#pragma unroll
            for (int off = 4; off <= 16; off <<= 1) {
                s0 += __shfl_down_sync(0xffffffffu, s0, off);
                s1 += __shfl_down_sync(0xffffffffu, s1, off);
                q0 += __shfl_down_sync(0xffffffffu, q0, off);
                q1 += __shfl_down_sync(0xffffffffu, q1, off);
            }
            if (group == 0) {
                atomicAdd(&statAcc[n], s0);
                atomicAdd(&statAcc[Dn + n], q0);
                atomicAdd(&statAcc[n + 1], s1);
                atomicAdd(&statAcc[Dn + n + 1], q1);
            }
        }
    }
}

__global__ void bn_prep(const float* __restrict__ acc, const float* __restrict__ gamma,
                        const float* __restrict__ beta, float inv_rows, float* __restrict__ coef)
{
    int d = threadIdx.x;
    float mu = acc[d] * inv_rows;
    float var = acc[Dn + d] * inv_rows - mu * mu;
    float sc = gamma[d] * rsqrtf(var + EPSn);
    coef[d] = sc;
    coef[Dn + d] = beta[d] - mu * sc;
}

__global__ void bn_apply(const float* __restrict__ c, const float* __restrict__ coef,
                         float* __restrict__ h, int n)
{
    int idx = blockIdx.x * blockDim.x + threadIdx.x;
    if (idx >= n) return;
    int d = idx & (Dn - 1);
    h[idx] = coef[d] * c[idx] + coef[Dn + d];
}

// ---------------- sub = mean over N (layer 0 only) ----------------
__global__ void submean_kernel(const float* __restrict__ x, float* __restrict__ sub)
{
    int b = blockIdx.x;
    int d = threadIdx.x;
    const float* xp = x + (size_t)b * Nn * Dn;
    float s = 0.f;
#pragma unroll 8
    for (int n = 0; n < Nn; n++) s += xp[n * Dn + d];
    sub[(size_t)b * Dn + d] = s * (1.f / Nn);
}

// ---------------- attention: per-graph 32x32, head-averaged softmax ----------------
__global__ void attn_kernel(const float* __restrict__ q, const float* __restrict__ k,
                            float* __restrict__ attn)
{
    int g = blockIdx.x;
    int tid = threadIdx.x;              // 128
    __shared__ float qs[Dn * 33];
    __shared__ float ks[Sn * Dn];
    __shared__ float at[Sn * Sn];
    const float* qg = q + (size_t)g * Sn * Dn;
    const float* kg = k + (size_t)g * Sn * Dn;
    for (int i = tid; i < Sn * Dn; i += 128) {
        int qi = i >> 7, c = i & 127;
        qs[c * 33 + qi] = qg[i];
        ks[i] = kg[i];
    }
    for (int i = tid; i < Sn * Sn; i += 128) at[i] = 0.f;
    __syncthreads();

    int h = tid >> 5;
    int qi = tid & 31;
    const float scale = 0.17677669529663687f;
    float sc[Sn];
    float mx = -1e30f;
#pragma unroll
    for (int j = 0; j < Sn; j++) {
        float dsum = 0.f;
#pragma unroll
        for (int hd = 0; hd < HDn; hd++)
            dsum += qs[(h * HDn + hd) * 33 + qi] * ks[j * Dn + h * HDn + hd];
        sc[j] = dsum * scale;
        mx = fmaxf(mx, sc[j]);
    }
    float se = 0.f;
#pragma unroll
    for (int j = 0; j < Sn; j++) { sc[j] = expf(sc[j] - mx); se += sc[j]; }
    float inv = 0.25f / se;
#pragma unroll
    for (int j = 0; j < Sn; j++) atomicAdd(&at[qi * Sn + j], sc[j] * inv);
    __syncthreads();
    for (int i = tid; i < Sn * Sn; i += 128) attn[(size_t)g * Sn * Sn + i] = at[i];
}

// ---------------- x_atten[g,n,d] = sum_s attn[g,s,n]*x[g,s,n,d] ----------------
__global__ void xatten_kernel(const float* __restrict__ x, const float* __restrict__ attn,
                              float* __restrict__ xatt)
{
    int b = blockIdx.x;
    int g = b >> 5, n = b & 31;
    int d = threadIdx.x;
    __shared__ float coef[Sn];
    if (d < Sn) coef[d] = attn[(size_t)g * Sn * Sn + d * Sn + n];
    __syncthreads();
    float acc = 0.f;
#pragma unroll 8
    for (int s = 0; s < Sn; s++)
        acc += coef[s] * x[(size_t)((g * Sn + s) * Nn + n) * Dn + d];
    xatt[(size_t)b * Dn + d] = acc;
}

// ---------------- combine: x = relu(BN1(c1) + h2 bcast); fused submean for next layer ----------------
__global__ void combine_fused(const float* __restrict__ c1, const float* __restrict__ coef1,
                              const float* __restrict__ h2, float* __restrict__ x,
                              float* __restrict__ sub)
{
    int b = blockIdx.x;          // g*Sn + s
    int g = b >> 5;
    int d = threadIdx.x;         // 128
    const float sc = coef1[d];
    const float sh = coef1[Dn + d];
    const float* c1p = c1 + (size_t)b * Nn * Dn;
    const float* h2p = h2 + (size_t)g * Nn * Dn;
    float* xp = x + (size_t)b * Nn * Dn;
    float s = 0.f;
#pragma unroll 4
    for (int n = 0; n < Nn; n++) {
        float v = fmaxf(sc * c1p[n * Dn + d] + sh + h2p[n * Dn + d], 0.f);
        xp[n * Dn + d] = v;
        s += v;
    }
    sub[(size_t)b * Dn + d] = s * (1.f / Nn);
}

// ---------------- graph pooling from sub ----------------
__global__ void pool_kernel(const float* __restrict__ sub, float* __restrict__ hg)
{
    int g = blockIdx.x;
    int d = threadIdx.x;
    float s = 0.f;
#pragma unroll 8
    for (int i = 0; i < Sn; i++) s += sub[(size_t)(g * Sn + i) * Dn + d];
    hg[(size_t)g * Dn + d] = s * (1.f / Sn);
}

// ---------------- MLP head ----------------
__global__ void mlp_kernel(const float* __restrict__ hg, const float* __restrict__ Wf1,
                           const float* __restrict__ bf1, const float* __restrict__ Wf2,
                           const float* __restrict__ bf2, float* __restrict__ out)
{
    int g = blockIdx.x;
    int tid = threadIdx.x;  // 256
    __shared__ float hv[Dn];
    __shared__ float hid[2 * Dn];
    if (tid < Dn) hv[tid] = hg[(size_t)g * Dn + tid];
    __syncthreads();
    float a = bf1[tid];
#pragma unroll 8
    for (int k2 = 0; k2 < Dn; k2++) a += hv[k2] * Wf1[(size_t)k2 * 2 * Dn + tid];
    hid[tid] = fmaxf(a, 0.f);
    __syncthreads();
    if (tid < NTASK) {
        float o = bf2[tid];
        for (int k2 = 0; k2 < 2 * Dn; k2++) o += hid[k2] * Wf2[(size_t)k2 * NTASK + tid];
        out[(size_t)g * NTASK + tid] = o;
    }
}

__global__ void heatmap_kernel(const float* __restrict__ attn, float* __restrict__ out)
{
    int i = blockIdx.x * blockDim.x + threadIdx.x;
    if (i < Sn * Sn) out[i] = attn[(size_t)(Gn - 1) * Sn * Sn + i];
}

// ---------------- host orchestration ----------------
extern "C" void kernel_launch(void* const* d_in, const int* in_sizes, int n_in,
                              void* d_out, int out_size)
{
    const float* x_in = (const float*)d_in[0];
    const int*   ei   = (const int*)d_in[1];
    const int*   oei  = (const int*)d_in[2];
    const float* Wr1 = (const float*)d_in[3];
    const float* Wn1 = (const float*)d_in[4];
    const float* b1  = (const float*)d_in[5];
    const float* g1  = (const float*)d_in[6];
    const float* be1 = (const float*)d_in[7];
    const float* Wr2 = (const float*)d_in[8];
    const float* Wn2 = (const float*)d_in[9];
    const float* b2  = (const float*)d_in[10];
    const float* g2  = (const float*)d_in[11];
    const float* be2 = (const float*)d_in[12];
    const float* Wq  = (const float*)d_in[13];
    const float* bq  = (const float*)d_in[14];
    const float* Wk  = (const float*)d_in[15];
    const float* bk  = (const float*)d_in[16];
    const float* Wf1 = (const float*)d_in[17];
    const float* bf1 = (const float*)d_in[18];
    const float* Wf2 = (const float*)d_in[19];
    const float* bf2 = (const float*)d_in[20];
    float* out = (float*)d_out;

    float *px, *pagg1, *pc1, *psub, *pq, *pk, *pattn, *pxatt, *pagg2, *pc2, *ph2, *pacc, *pcoef, *phg;
    int *pdeg, *poff, *pcur, *psrcs, *podeg, *pooff, *pocur, *posrcs;
    cudaGetSymbolAddress((void**)&px,    g_x);
    cudaGetSymbolAddress((void**)&pagg1, g_agg1);
    cudaGetSymbolAddress((void**)&pc1,   g_c1);
    cudaGetSymbolAddress((void**)&psub,  g_sub);
    cudaGetSymbolAddress((void**)&pq,    g_q);
    cudaGetSymbolAddress((void**)&pk,    g_k);
    cudaGetSymbolAddress((void**)&pattn, g_attn);
    cudaGetSymbolAddress((void**)&pxatt, g_xatt);
    cudaGetSymbolAddress((void**)&pagg2, g_agg2);
    cudaGetSymbolAddress((void**)&pc2,   g_c2);
    cudaGetSymbolAddress((void**)&ph2,   g_h2);
    cudaGetSymbolAddress((void**)&pacc,  g_acc);
    cudaGetSymbolAddress((void**)&pcoef, g_coef);
    cudaGetSymbolAddress((void**)&phg,   g_hg);
    cudaGetSymbolAddress((void**)&pdeg,  g_deg);
    cudaGetSymbolAddress((void**)&poff,  g_off);
    cudaGetSymbolAddress((void**)&pcur,  g_cur);
    cudaGetSymbolAddress((void**)&psrcs, g_srcs);
    cudaGetSymbolAddress((void**)&podeg, g_odeg);
    cudaGetSymbolAddress((void**)&pooff, g_ooff);
    cudaGetSymbolAddress((void**)&pocur, g_ocur);
    cudaGetSymbolAddress((void**)&posrcs, g_osrcs);

    // ---- build CSR for both graphs (once per launch; reused across layers) ----
    cudaMemsetAsync(pdeg,  0, sizeof(int) * Tn, 0);
    cudaMemsetAsync(podeg, 0, sizeof(int) * TOn, 0);
    hist_kernel<<<En / 256, 256>>>(ei + En, pdeg, En);
    hist_kernel<<<EOn / 256, 256>>>(oei + EOn, podeg, EOn);
    scan_kernel<<<1, 1024>>>(pdeg, poff, pcur, Tn);
    scan_kernel<<<1, 1024>>>(podeg, pooff, pocur, TOn);
    fill_kernel<<<En / 256, 256>>>(ei, ei + En, pcur, psrcs, En);
    fill_kernel<<<EOn / 256, 256>>>(oei, oei + EOn, pocur, posrcs, EOn);

    const float* xcur = x_in;

    for (int i = 0; i < Ln; i++) {
        const size_t wOff = (size_t)i * Dn * Dn;
        const size_t vOff = (size_t)i * Dn;

        cudaMemsetAsync(pacc, 0, sizeof(float) * 512, 0);

        // subgraph-level GraphConv (+ fused BN stats)
        gather_kernel<<<(Tn * 32) / 256, 256>>>(xcur, poff, psrcs, pagg1, Tn);
        conv_gemm_tf32<<<Tn / 128, 256>>>(xcur, pagg1, Wr1 + wOff, Wn1 + wOff, b1 + vOff, pc1, pacc,
                                          nullptr, nullptr, nullptr);
        bn_prep<<<1, 128>>>(pacc, g1 + vOff, be1 + vOff, 1.f / Tn, pcoef);

        // attention branch (sub produced by previous combine, except layer 0)
        if (i == 0) submean_kernel<<<Gn * Sn, 128>>>(xcur, psub);
        conv_gemm_tf32<<<dim3((Gn * Sn) / 128, 2), 256>>>(psub, nullptr, Wq + wOff, nullptr,
                                                          bq + vOff, pq, nullptr,
                                                          Wk + wOff, bk + vOff, pk);
        attn_kernel<<<Gn, 128>>>(pq, pk, pattn);
        xatten_kernel<<<Gn * Nn, 128>>>(xcur, pattn, pxatt);

        // original-graph GraphConv (+ fused BN stats)
        gather_kernel<<<(TOn * 32) / 256, 256>>>(pxatt, pooff, posrcs, pagg2, TOn);
        conv_gemm_tf32<<<TOn / 128, 256>>>(pxatt, pagg2, Wr2 + wOff, Wn2 + wOff, b2 + vOff, pc2,
                                           pacc + 256, nullptr, nullptr, nullptr);
        bn_prep<<<1, 128>>>(pacc + 256, g2 + vOff, be2 + vOff, 1.f / TOn, pcoef + 256);
        bn_apply<<<(TOn * Dn) / 256, 256>>>(pc2, pcoef + 256, ph2, TOn * Dn);

        // x = relu(h1 + h2 broadcast); sub for next layer fused
        combine_fused<<<Gn * Sn, 128>>>(pc1, pcoef, ph2, px, psub);
        xcur = px;
    }

    pool_kernel<<<Gn, 128>>>(psub, phg);
    mlp_kernel<<<Gn, 256>>>(phg, Wf1, bf1, Wf2, bf2, out);
    heatmap_kernel<<<4, 256>>>(pattn, out + Gn * NTASK);
}